// round 16
// baseline (speedup 1.0000x reference)
#include <cuda_runtime.h>
#include <cuda_bf16.h>
#include <cstdint>

// ---------------------------------------------------------------------------
// JointRetriveDeformHead — round 15
//  * k_decode_mlp: 2 (b,k) instances per block (grid 320). decW2 limb
//    B-fragments shared between warp pairs (L1 reuse, halves L2 latency
//    stalls); A tiles (32 parts) overlaid by H2f after MMA (smem ~42KB,
//    4 CTAs/SM); raw/proj tails on 192 threads.
//  * Rest = round-14 passing code (332.9 us best).
// ---------------------------------------------------------------------------

#define B_      64
#define S_      1024
#define D_      256
#define KRET    10
#define NPART   16
#define NPAR    96
#define PSRC3   1536

__device__ float g_pool[2 * B_ * D_];
__device__ float g_T   [B_ * D_];
__device__ int   g_idx [B_ * KRET];
__device__ float g_par [B_ * KRET * NPAR];
__device__ float g_SC1 [S_ * D_];
__device__ float g_P1  [S_ * NPART * D_];
__device__ float g_varT[D_ * S_];
__device__ float g_rscT[D_ * S_];
__device__ unsigned short g_A3h[2 * 256 * 128];
__device__ unsigned short g_A3l[2 * 256 * 128];
__device__ unsigned short g_dW2h[256 * 256];      // [ks][ch][16kin]
__device__ unsigned short g_dW2l[256 * 256];

typedef unsigned long long u64;

__device__ __forceinline__ u64 pk(float lo, float hi) {
    u64 r; asm("mov.b64 %0,{%1,%2};" : "=l"(r) : "f"(lo), "f"(hi)); return r;
}
__device__ __forceinline__ void upk(u64 v, float& lo, float& hi) {
    asm("mov.b64 {%0,%1},%2;" : "=f"(lo), "=f"(hi) : "l"(v));
}
__device__ __forceinline__ u64 fma2(u64 a, u64 b, u64 c) {
    u64 d; asm("fma.rn.f32x2 %0,%1,%2,%3;" : "=l"(d) : "l"(a), "l"(b), "l"(c)); return d;
}
__device__ __forceinline__ void split_bf16(float v, unsigned short& h, unsigned short& l) {
    __nv_bfloat16 bh = __float2bfloat16(v);
    float fh = __bfloat162float(bh);
    __nv_bfloat16 bl = __float2bfloat16(v - fh);
    h = __bfloat16_as_ushort(bh);
    l = __bfloat16_as_ushort(bl);
}

#define MMA16816(d0,d1,d2,d3,a0,a1,a2,a3,b0,b1) \
    asm volatile("mma.sync.aligned.m16n8k16.row.col.f32.bf16.bf16.f32 " \
        "{%0,%1,%2,%3}, {%4,%5,%6,%7}, {%8,%9}, {%0,%1,%2,%3};" \
        : "+f"(d0),"+f"(d1),"+f"(d2),"+f"(d3) \
        : "r"(a0),"r"(a1),"r"(a2),"r"(a3),"r"(b0),"r"(b1))

// pointnet dynamic smem layout (bytes)
#define OFF_ALO 0
#define OFF_BH  69632
#define OFF_BL  78336
#define OFF_H1  87040
#define OFF_X   96256
#define SMEMSZ  96640

// ---------------------------------------------------------------------------
// k_prep — fused prep. grid 1920, 256 threads. (round-14 form)
// ---------------------------------------------------------------------------
__global__ __launch_bounds__(256)
void k_prep(const float* __restrict__ var,  const float* __restrict__ rsc,
            const float* __restrict__ teW3, const float* __restrict__ reW3,
            const float* __restrict__ decW2,
            const float* __restrict__ src_codes,
            const float* __restrict__ decW1, const float* __restrict__ decb1,
            const float* __restrict__ part_latent)
{
    __shared__ __align__(16) char prepsm[8448];
    const int bid = blockIdx.x, t = threadIdx.x;

    if (bid < 256) {
        float (*tv)[33] = (float(*)[33])prepsm;
        float (*tr)[33] = (float(*)[33])(prepsm + 4224);
        const int tx = t & 31, ty = t >> 5;
        const int s0 = (bid & 31) * 32, k0 = (bid >> 5) * 32;
        #pragma unroll
        for (int jj = 0; jj < 4; ++jj) {
            int s = s0 + ty + jj * 8;
            tv[ty + jj * 8][tx] = var[s * D_ + k0 + tx];
            tr[ty + jj * 8][tx] = rsc[s * D_ + k0 + tx];
        }
        __syncthreads();
        #pragma unroll
        for (int jj = 0; jj < 4; ++jj) {
            int k = k0 + ty + jj * 8;
            g_varT[k * S_ + s0 + tx] = tv[tx][ty + jj * 8];
            g_rscT[k * S_ + s0 + tx] = tr[tx][ty + jj * 8];
        }
    } else if (bid < 512) {
        int idx = (bid - 256) * 256 + t;
        int enc = idx >> 15;
        int r   = idx & 32767;
        int ch  = r >> 7;
        int k   = r & 127;
        const float* W3 = enc ? reW3 : teW3;
        float w = W3[k * 256 + ch];
        unsigned short h, l;
        split_bf16(w, h, l);
        g_A3h[idx] = h;
        g_A3l[idx] = l;
    } else if (bid < 768) {
        int idx = (bid - 512) * 256 + t;       // k*256+ch
        int k  = idx >> 8;
        int ch = idx & 255;
        float w = decW2[k * 256 + ch];
        unsigned short h, l;
        split_bf16(w, h, l);
        int ks = k >> 4, kin = k & 15;
        g_dW2h[(ks * 256 + ch) * 16 + kin] = h;
        g_dW2l[(ks * 256 + ch) * 16 + kin] = l;
    } else if (bid < 896) {
        float (*scs)[256] = (float(*)[256])prepsm;
        const int s0 = (bid - 768) * 8;
        #pragma unroll
        for (int q = 0; q < 8; ++q)
            scs[q][t] = src_codes[(s0 + q) * 256 + t];
        __syncthreads();
        float acc[8];
        float bb = decb1[t];
        #pragma unroll
        for (int q = 0; q < 8; ++q) acc[q] = bb;
        #pragma unroll 4
        for (int i = 0; i < 256; ++i) {
            float w = decW1[(256 + i) * 256 + t];
            #pragma unroll
            for (int q = 0; q < 8; ++q)
                acc[q] = fmaf(scs[q][i], w, acc[q]);
        }
        #pragma unroll
        for (int q = 0; q < 8; ++q)
            g_SC1[(s0 + q) * 256 + t] = acc[q];
    } else {
        float (*part)[32] = (float(*)[32])prepsm;
        const int s = bid - 896;
        ((float*)part)[t]       = part_latent[s * (NPART * 32) + t];
        ((float*)part)[t + 256] = part_latent[s * (NPART * 32) + t + 256];
        __syncthreads();
        float wt[32];
        #pragma unroll
        for (int i = 0; i < 32; ++i)
            wt[i] = decW1[(512 + i) * 256 + t];
        #pragma unroll 2
        for (int p = 0; p < NPART; ++p) {
            float v = 0.f;
            #pragma unroll
            for (int i = 0; i < 32; ++i)
                v = fmaf(part[p][i], wt[i], v);
            g_P1[(s * NPART + p) * 256 + t] = v;
        }
    }
}

// ---------------------------------------------------------------------------
// Kernel 1: PointNet (round-12 exact). grid (64,2), 256 threads.
// ---------------------------------------------------------------------------
__global__ __launch_bounds__(256, 1)
void k_pointnet(const float* __restrict__ noc,
                const float* __restrict__ teW1, const float* __restrict__ teb1,
                const float* __restrict__ teW2, const float* __restrict__ teb2,
                const float* __restrict__ teb3,
                const float* __restrict__ reW1, const float* __restrict__ reb1,
                const float* __restrict__ reW2, const float* __restrict__ reb2,
                const float* __restrict__ reb3)
{
    extern __shared__ char smem[];
    const int b = blockIdx.x;
    const int enc = blockIdx.y;
    const float* W1 = enc ? reW1 : teW1; const float* b1 = enc ? reb1 : teb1;
    const float* W2 = enc ? reW2 : teW2; const float* b2 = enc ? reb2 : teb2;
    const float* b3 = enc ? reb3 : teb3;

    const int t = threadIdx.x;
    const int warp = t >> 5, lane = t & 31;
    const int g = lane >> 2, j = lane & 3;

    unsigned short* ALO = (unsigned short*)(smem + OFF_ALO);
    unsigned short* BHs = (unsigned short*)(smem + OFF_BH);
    unsigned short* BLs = (unsigned short*)(smem + OFF_BL);
    float* H1c = (float*)(smem + OFF_H1);
    float* Xf  = (float*)(smem + OFF_X);
    const uint32_t* ALO32 = (const uint32_t*)ALO;
    const uint32_t* BH32  = (const uint32_t*)BHs;
    const uint32_t* BL32  = (const uint32_t*)BLs;

    {
        const uint4* src = (const uint4*)(g_A3l + enc * 32768);
        #pragma unroll
        for (int i = 0; i < 16; ++i)
            *(uint4*)(ALO + t * 136 + i * 8) = src[t * 16 + i];
    }

    uint32_t ahi[64];
    {
        const uint32_t* AH = (const uint32_t*)(g_A3h + enc * 32768);
        #pragma unroll
        for (int mt = 0; mt < 2; ++mt) {
            const int r0 = warp * 32 + mt * 16 + g;
            #pragma unroll
            for (int ks = 0; ks < 8; ++ks) {
                const int fi = (mt * 8 + ks) * 4;
                ahi[fi + 0] = AH[r0 * 64 + j + 8 * ks];
                ahi[fi + 1] = AH[(r0 + 8) * 64 + j + 8 * ks];
                ahi[fi + 2] = AH[r0 * 64 + j + 4 + 8 * ks];
                ahi[fi + 3] = AH[(r0 + 8) * 64 + j + 4 + 8 * ks];
            }
        }
    }

    const int colB = t & 63, pgB = t >> 6;
    const int c0C = (t & 31) * 4, pgC = t >> 5;
    const float w10 = W1[colB], w11 = W1[64 + colB], w12 = W1[128 + colB];
    const float bb1 = b1[colB];
    const float4 bb2 = *(const float4*)&b2[c0C];
    const u64 bb2p[4] = { pk(bb2.x, bb2.x), pk(bb2.y, bb2.y),
                          pk(bb2.z, bb2.z), pk(bb2.w, bb2.w) };

    float dmax[4] = { -1e30f, -1e30f, -1e30f, -1e30f };

    #pragma unroll 1
    for (int chunk = 0; chunk < 32; ++chunk) {
        __syncthreads();
        if (t < 96) {
            int c = t >> 5, p = t & 31;
            Xf[c * 32 + p] = noc[b * 3072 + c * 1024 + chunk * 32 + p];
        }
        __syncthreads();

        {
            float v[8];
            #pragma unroll
            for (int pp = 0; pp < 8; ++pp) {
                int p = pgB * 8 + pp;
                float h = fmaf(Xf[p], w10, fmaf(Xf[32 + p], w11, fmaf(Xf[64 + p], w12, bb1)));
                v[pp] = fmaxf(h, 0.f);
            }
            #pragma unroll
            for (int q = 0; q < 4; ++q)
                *(u64*)&H1c[colB * 36 + pgB * 8 + 2 * q] = pk(v[2*q], v[2*q+1]);
        }
        __syncthreads();

        {
            u64 acc[2][4];
            #pragma unroll
            for (int q = 0; q < 2; ++q)
                #pragma unroll
                for (int jj = 0; jj < 4; ++jj) acc[q][jj] = bb2p[jj];
            #pragma unroll 4
            for (int k = 0; k < 64; ++k) {
                ulonglong2 xa = *(const ulonglong2*)&H1c[k * 36 + pgC * 4];
                float4 w = *(const float4*)&W2[k * 128 + c0C];
                u64 wp0 = pk(w.x, w.x), wp1 = pk(w.y, w.y);
                u64 wp2 = pk(w.z, w.z), wp3 = pk(w.w, w.w);
                acc[0][0] = fma2(xa.x, wp0, acc[0][0]);
                acc[0][1] = fma2(xa.x, wp1, acc[0][1]);
                acc[0][2] = fma2(xa.x, wp2, acc[0][2]);
                acc[0][3] = fma2(xa.x, wp3, acc[0][3]);
                acc[1][0] = fma2(xa.y, wp0, acc[1][0]);
                acc[1][1] = fma2(xa.y, wp1, acc[1][1]);
                acc[1][2] = fma2(xa.y, wp2, acc[1][2]);
                acc[1][3] = fma2(xa.y, wp3, acc[1][3]);
            }
            float vals[4][4];
            #pragma unroll
            for (int q = 0; q < 2; ++q)
                #pragma unroll
                for (int jj = 0; jj < 4; ++jj)
                    upk(acc[q][jj], vals[2*q][jj], vals[2*q+1][jj]);
            #pragma unroll
            for (int p = 0; p < 4; ++p) {
                int n = pgC * 4 + p;
                unsigned short h[4], l[4];
                #pragma unroll
                for (int jj = 0; jj < 4; ++jj)
                    split_bf16(fmaxf(vals[p][jj], 0.f), h[jj], l[jj]);
                u64 hp = (u64)h[0] | ((u64)h[1] << 16) | ((u64)h[2] << 32) | ((u64)h[3] << 48);
                u64 lp = (u64)l[0] | ((u64)l[1] << 16) | ((u64)l[2] << 32) | ((u64)l[3] << 48);
                *(u64*)((char*)BHs + n * 272 + c0C * 2) = hp;
                *(u64*)((char*)BLs + n * 272 + c0C * 2) = lp;
            }
        }
        __syncthreads();

        float d[2][4][4];
        #pragma unroll
        for (int mt = 0; mt < 2; ++mt)
            #pragma unroll
            for (int nt = 0; nt < 4; ++nt)
                #pragma unroll
                for (int e = 0; e < 4; ++e) d[mt][nt][e] = 0.f;

        #pragma unroll
        for (int ks = 0; ks < 8; ++ks) {
            uint32_t bh0[4], bh1[4], bl0[4], bl1[4];
            #pragma unroll
            for (int nt = 0; nt < 4; ++nt) {
                const uint32_t* BHrow = BH32 + (nt * 8 + g) * 68;
                const uint32_t* BLrow = BL32 + (nt * 8 + g) * 68;
                bh0[nt] = BHrow[j + 8 * ks];
                bh1[nt] = BHrow[j + 4 + 8 * ks];
                bl0[nt] = BLrow[j + 8 * ks];
                bl1[nt] = BLrow[j + 4 + 8 * ks];
            }
            #pragma unroll
            for (int mt = 0; mt < 2; ++mt) {
                const int fi = (mt * 8 + ks) * 4;
                uint32_t a0 = ahi[fi], a1 = ahi[fi+1], a2 = ahi[fi+2], a3 = ahi[fi+3];
                #pragma unroll
                for (int nt = 0; nt < 4; ++nt) {
                    MMA16816(d[mt][nt][0], d[mt][nt][1], d[mt][nt][2], d[mt][nt][3],
                             a0, a1, a2, a3, bh0[nt], bh1[nt]);
                    MMA16816(d[mt][nt][0], d[mt][nt][1], d[mt][nt][2], d[mt][nt][3],
                             a0, a1, a2, a3, bl0[nt], bl1[nt]);
                }
                const int r0 = warp * 32 + mt * 16 + g;
                uint32_t l0 = ALO32[r0 * 68 + j + 8 * ks];
                uint32_t l1 = ALO32[(r0 + 8) * 68 + j + 8 * ks];
                uint32_t l2 = ALO32[r0 * 68 + j + 4 + 8 * ks];
                uint32_t l3 = ALO32[(r0 + 8) * 68 + j + 4 + 8 * ks];
                #pragma unroll
                for (int nt = 0; nt < 4; ++nt)
                    MMA16816(d[mt][nt][0], d[mt][nt][1], d[mt][nt][2], d[mt][nt][3],
                             l0, l1, l2, l3, bh0[nt], bh1[nt]);
            }
        }

        #pragma unroll
        for (int mt = 0; mt < 2; ++mt)
            #pragma unroll
            for (int nt = 0; nt < 4; ++nt) {
                dmax[mt*2+0] = fmaxf(dmax[mt*2+0], fmaxf(d[mt][nt][0], d[mt][nt][1]));
                dmax[mt*2+1] = fmaxf(dmax[mt*2+1], fmaxf(d[mt][nt][2], d[mt][nt][3]));
            }
    }

    #pragma unroll
    for (int e = 0; e < 4; ++e) {
        dmax[e] = fmaxf(dmax[e], __shfl_xor_sync(0xffffffffu, dmax[e], 1));
        dmax[e] = fmaxf(dmax[e], __shfl_xor_sync(0xffffffffu, dmax[e], 2));
    }
    if (j == 0) {
        #pragma unroll
        for (int mt = 0; mt < 2; ++mt)
            #pragma unroll
            for (int hf = 0; hf < 2; ++hf) {
                int ch = warp * 32 + mt * 16 + hf * 8 + g;
                g_pool[(enc * B_ + b) * D_ + ch] = fmaxf(dmax[mt*2+hf] + b3[ch], 0.f);
            }
    }
}

// ---------------------------------------------------------------------------
// Kernel 2: fused fc + distances + exact top-10. grid 64, 256 threads.
// ---------------------------------------------------------------------------
__global__ __launch_bounds__(256, 1)
void k_fcdist(const float* __restrict__ teWf, const float* __restrict__ tebf,
              const float* __restrict__ reWf, const float* __restrict__ rebf,
              const float* __restrict__ decW1)
{
    const int b = blockIdx.x, t = threadIdx.x;
    __shared__ float ste[256], rets[256], stgt[256];
    __shared__ float d[1024];
    __shared__ float sval[256];
    __shared__ int   sidx[256];

    ste[t] = g_pool[b * D_ + t];
    d[t]   = g_pool[(B_ + b) * D_ + t];
    __syncthreads();

    float a = tebf[t], r = rebf[t];
    #pragma unroll 8
    for (int i = 0; i < 256; ++i) {
        a = fmaf(ste[i], teWf[i * 256 + t], a);
        r = fmaf(d[i],   reWf[i * 256 + t], r);
    }
    rets[t] = r;
    stgt[t] = a;
    __syncthreads();

    float tv = 0.f;
    #pragma unroll 8
    for (int i = 0; i < 256; ++i)
        tv = fmaf(stgt[i], decW1[i * 256 + t], tv);
    g_T[b * D_ + t] = tv;

    const int s4 = 4 * t;
    float a0 = 0.f, a1 = 0.f, a2 = 0.f, a3 = 0.f;
    #pragma unroll 4
    for (int k = 0; k < 256; ++k) {
        float rr = rets[k];
        float4 v = *(const float4*)&g_varT[k * S_ + s4];
        float4 c = *(const float4*)&g_rscT[k * S_ + s4];
        float d0 = rr - c.x, d1 = rr - c.y, d2 = rr - c.z, d3 = rr - c.w;
        a0 = fmaf(v.x, d0 * d0, a0);
        a1 = fmaf(v.y, d1 * d1, a1);
        a2 = fmaf(v.z, d2 * d2, a2);
        a3 = fmaf(v.w, d3 * d3, a3);
    }
    d[s4] = a0; d[s4 + 1] = a1; d[s4 + 2] = a2; d[s4 + 3] = a3;
    __syncthreads();

    for (int it = 0; it < KRET; ++it) {
        float bv = 1e30f; int bi = S_;
        #pragma unroll
        for (int q = 0; q < 4; ++q) {
            int s = q * 256 + t;
            float v = d[s];
            if (v < bv || (v == bv && s < bi)) { bv = v; bi = s; }
        }
        sval[t] = bv; sidx[t] = bi;
        __syncthreads();
        for (int off = 128; off > 0; off >>= 1) {
            if (t < off) {
                float v2 = sval[t + off]; int i2 = sidx[t + off];
                if (v2 < sval[t] || (v2 == sval[t] && i2 < sidx[t])) {
                    sval[t] = v2; sidx[t] = i2;
                }
            }
            __syncthreads();
        }
        if (t == 0) {
            g_idx[b * KRET + it] = sidx[0];
            d[sidx[0]] = 1e30f;
        }
        __syncthreads();
    }
}

// ---------------------------------------------------------------------------
// Kernel 4: decoder MLP via mma.sync, 2 bk per block. grid 320, 256 thr.
// Warp w: mt = w&1 (bk), chs [(w>>1)*64, +64) = 8 n8-tiles. Warp pairs
// (2i, 2i+1) read identical B fragments -> L1 reuse.
// H2f overlays the A tiles after MMA (sync-protected).
// ---------------------------------------------------------------------------
__global__ __launch_bounds__(256, 4)
void k_decode_mlp(const float* __restrict__ decb2,
                  const float* __restrict__ decW3, const float* __restrict__ decb3,
                  const float* __restrict__ proj,  const float* __restrict__ defp)
{
    const int bk0 = blockIdx.x * 2;
    const int t = threadIdx.x;
    const int warp = t >> 5, lane = t & 31;
    const int g = lane >> 2, j = lane & 3;

    __shared__ __align__(16) char usm[40960 + 1024];
    unsigned short* AH1 = (unsigned short*)usm;            // [32][264] = 16896B
    unsigned short* AL1 = AH1 + 32 * 264;                  // [32][264]
    __shared__ float raw[2][NPAR];

    // ---- H1 limbs for both bks (k-col = t) ----
    #pragma unroll
    for (int bkl = 0; bkl < 2; ++bkl) {
        const int bk = bk0 + bkl;
        const int b = bk / KRET;
        const int s = g_idx[bk];
        float base = g_T[b * D_ + t] + g_SC1[s * 256 + t];
        const float* p1 = &g_P1[s * (NPART * 256) + t];
        #pragma unroll
        for (int p = 0; p < NPART; ++p) {
            float v = fmaxf(base + p1[p * 256], 0.f);
            unsigned short h, l;
            split_bf16(v, h, l);
            AH1[(bkl * 16 + p) * 264 + t] = h;
            AL1[(bkl * 16 + p) * 264 + t] = l;
        }
    }
    __syncthreads();

    // ---- H2 via MMA: warp: mt = w&1, 8 n8-tiles of 8 chs; 16 ksteps ----
    const int mt = warp & 1;
    const int chb = (warp >> 1) * 64;
    float d[8][4];
    {
        const uint32_t* A1H32 = (const uint32_t*)AH1;   // [32][132]
        const uint32_t* A1L32 = (const uint32_t*)AL1;
        const uint32_t* WH32 = (const uint32_t*)g_dW2h;
        const uint32_t* WL32 = (const uint32_t*)g_dW2l;

        #pragma unroll
        for (int nt = 0; nt < 8; ++nt)
            #pragma unroll
            for (int e = 0; e < 4; ++e) d[nt][e] = 0.f;

        const int r0 = mt * 16 + g;
        #pragma unroll 2
        for (int ks = 0; ks < 16; ++ks) {
            uint32_t ah0 = A1H32[r0 * 132 + j + 8 * ks];
            uint32_t ah1 = A1H32[(r0 + 8) * 132 + j + 8 * ks];
            uint32_t ah2 = A1H32[r0 * 132 + j + 4 + 8 * ks];
            uint32_t ah3 = A1H32[(r0 + 8) * 132 + j + 4 + 8 * ks];
            uint32_t al0 = A1L32[r0 * 132 + j + 8 * ks];
            uint32_t al1 = A1L32[(r0 + 8) * 132 + j + 8 * ks];
            uint32_t al2 = A1L32[r0 * 132 + j + 4 + 8 * ks];
            uint32_t al3 = A1L32[(r0 + 8) * 132 + j + 4 + 8 * ks];
            #pragma unroll
            for (int nt = 0; nt < 8; ++nt) {
                const int ch = chb + nt * 8 + g;
                const uint32_t* Wh = WH32 + (ks * 256 + ch) * 8;
                const uint32_t* Wl = WL32 + (ks * 256 + ch) * 8;
                uint32_t bh0 = Wh[j], bh1 = Wh[j + 4];
                uint32_t bl0 = Wl[j], bl1 = Wl[j + 4];
                MMA16816(d[nt][0], d[nt][1], d[nt][2], d[nt][3],
                         ah0, ah1, ah2, ah3, bh0, bh1);
                MMA16816(d[nt][0], d[nt][1], d[nt][2], d[nt][3],
                         ah0, ah1, ah2, ah3, bl0, bl1);
                MMA16816(d[nt][0], d[nt][1], d[nt][2], d[nt][3],
                         al0, al1, al2, al3, bh0, bh1);
            }
        }
    }
    __syncthreads();   // all A reads complete -> usm reusable as H2f

    // ---- epilogue: bias + relu -> H2f[bk][ch][20] (overlays A tiles) ----
    float* H2base = (float*)usm;                    // [2][256][20] = 40960B
    {
        float* H2 = H2base + mt * 5120;
        #pragma unroll
        for (int nt = 0; nt < 8; ++nt) {
            const int ch0 = chb + nt * 8 + 2 * j;
            float bb0 = decb2[ch0], bb1 = decb2[ch0 + 1];
            H2[ch0 * 20 + g]           = fmaxf(d[nt][0] + bb0, 0.f);
            H2[(ch0 + 1) * 20 + g]     = fmaxf(d[nt][1] + bb1, 0.f);
            H2[ch0 * 20 + g + 8]       = fmaxf(d[nt][2] + bb0, 0.f);
            H2[(ch0 + 1) * 20 + g + 8] = fmaxf(d[nt][3] + bb1, 0.f);
        }
    }
    __syncthreads();

    // ---- raw = H2 @ W3 + b3 (192 threads: 2 bk x 96) ----
    if (t < 192) {
        const int bkl = t / 96, tt = t % 96;
        const int p = tt / 6, o = tt % 6;
        const float* H2 = H2base + bkl * 5120;
        float v = decb3[o];
        #pragma unroll 8
        for (int k = 0; k < 256; ++k)
            v = fmaf(H2[k * 20 + p], decW3[k * 6 + o], v);
        raw[bkl][tt] = v;
    }
    __syncthreads();

    // ---- params = proj[s] @ raw + def[s] ----
    if (t < 192) {
        const int bkl = t / 96, tt = t % 96;
        const int s = g_idx[bk0 + bkl];
        float v = defp[s * NPAR + tt];
        const float* pr = proj + (size_t)s * NPAR * NPAR + tt * NPAR;
        #pragma unroll 8
        for (int jj = 0; jj < NPAR; ++jj)
            v = fmaf(pr[jj], raw[bkl][jj], v);
        g_par[(bk0 + bkl) * NPAR + tt] = v;
    }
}

// ---------------------------------------------------------------------------
// Kernel 5: deformation (round-12 smem-staged form). grid (640, 6).
// ---------------------------------------------------------------------------
__global__ __launch_bounds__(256)
void k_deform(const float* __restrict__ mat, float* __restrict__ out)
{
    const int bk = blockIdx.x;
    const int t = threadIdx.x;
    const int s = g_idx[bk];
    __shared__ float par[NPAR];
    __shared__ __align__(16) float tilebuf[64 * 104];
    if (t < NPAR) par[t] = g_par[bk * NPAR + t];

    const float* mb = mat + (size_t)s * PSRC3 * NPAR;
    float* ob = out + (size_t)bk * PSRC3;
    const int row = t >> 2, q = t & 3;

    #pragma unroll 1
    for (int tile = 0; tile < 4; ++tile) {
        const int R0 = blockIdx.y * 256 + tile * 64;
        __syncthreads();
        const float4* src = (const float4*)(mb + (size_t)R0 * NPAR);
        #pragma unroll
        for (int i = 0; i < 6; ++i) {
            int idx = i * 256 + t;
            int r = idx / 24, c = idx % 24;
            *(float4*)&tilebuf[r * 104 + c * 4] = src[idx];
        }
        __syncthreads();
        float v = 0.f;
        const float* tb = &tilebuf[row * 104 + q * 24];
        const float* pq = &par[q * 24];
        #pragma unroll
        for (int i4 = 0; i4 < 6; ++i4) {
            float4 m4 = *(const float4*)&tb[i4 * 4];
            v = fmaf(m4.x, pq[i4 * 4 + 0], v);
            v = fmaf(m4.y, pq[i4 * 4 + 1], v);
            v = fmaf(m4.z, pq[i4 * 4 + 2], v);
            v = fmaf(m4.w, pq[i4 * 4 + 3], v);
        }
        v += __shfl_xor_sync(0xffffffffu, v, 1);
        v += __shfl_xor_sync(0xffffffffu, v, 2);
        if (q == 0)
            ob[R0 + row] = v;
    }
}

// ---------------------------------------------------------------------------
extern "C" void kernel_launch(void* const* d_in, const int* in_sizes, int n_in,
                              void* d_out, int out_size)
{
    const float* noc  = (const float*)d_in[0];
    const float* teW1 = (const float*)d_in[1];  const float* teb1 = (const float*)d_in[2];
    const float* teW2 = (const float*)d_in[3];  const float* teb2 = (const float*)d_in[4];
    const float* teW3 = (const float*)d_in[5];  const float* teb3 = (const float*)d_in[6];
    const float* teWf = (const float*)d_in[7];  const float* tebf = (const float*)d_in[8];
    const float* reW1 = (const float*)d_in[9];  const float* reb1 = (const float*)d_in[10];
    const float* reW2 = (const float*)d_in[11]; const float* reb2 = (const float*)d_in[12];
    const float* reW3 = (const float*)d_in[13]; const float* reb3 = (const float*)d_in[14];
    const float* reWf = (const float*)d_in[15]; const float* rebf = (const float*)d_in[16];
    const float* decW1 = (const float*)d_in[17]; const float* decb1 = (const float*)d_in[18];
    const float* decW2 = (const float*)d_in[19]; const float* decb2 = (const float*)d_in[20];
    const float* decW3 = (const float*)d_in[21]; const float* decb3 = (const float*)d_in[22];
    const float* ret_src = (const float*)d_in[23];
    const float* src_codes = (const float*)d_in[24];
    const float* src_var = (const float*)d_in[25];
    const float* part_latent = (const float*)d_in[26];
    const float* defp = (const float*)d_in[27];
    const float* proj = (const float*)d_in[28];
    const float* mat  = (const float*)d_in[29];
    float* out = (float*)d_out;

    cudaFuncSetAttribute(k_pointnet, cudaFuncAttributeMaxDynamicSharedMemorySize, SMEMSZ);

    k_prep<<<1920, 256>>>(src_var, ret_src, teW3, reW3, decW2,
                          src_codes, decW1, decb1, part_latent);
    dim3 g1(B_, 2);
    k_pointnet<<<g1, 256, SMEMSZ>>>(noc, teW1, teb1, teW2, teb2, teb3,
                                    reW1, reb1, reW2, reb2, reb3);
    k_fcdist<<<B_, 256>>>(teWf, tebf, reWf, rebf, decW1);
    k_decode_mlp<<<B_ * KRET / 2, 256>>>(decb2, decW3, decb3, proj, defp);
    dim3 g5(B_ * KRET, 6);
    k_deform<<<g5, 256>>>(mat, out);
}

// round 17
// speedup vs baseline: 1.0660x; 1.0660x over previous
#include <cuda_runtime.h>
#include <cuda_bf16.h>
#include <cstdint>

// ---------------------------------------------------------------------------
// JointRetriveDeformHead — round 16
//  * decode REVERTED to round-14 structure (grid 640, occ was the binding
//    resource), but decW2 limbs repacked so each lane's 4 fragment words
//    (bh0,bh1,bl0,bl1) are ONE LDG.128: 256 -> 64 B-LDGs per thread.
//  * prep split: k_prepW3 (needed by pointnet, main stream) + k_prepRest
//    (transpose/dW2/SC1/P1) forked onto stream s2, overlapping pointnet on
//    the 20 idle SMs; joined before k_fcdist.
//  * pointnet / fcdist / deform = round-14 passing code (332.9 us best).
// ---------------------------------------------------------------------------

#define B_      64
#define S_      1024
#define D_      256
#define KRET    10
#define NPART   16
#define NPAR    96
#define PSRC3   1536

__device__ float g_pool[2 * B_ * D_];
__device__ float g_T   [B_ * D_];
__device__ int   g_idx [B_ * KRET];
__device__ float g_par [B_ * KRET * NPAR];
__device__ float g_SC1 [S_ * D_];
__device__ float g_P1  [S_ * NPART * D_];
__device__ float g_varT[D_ * S_];
__device__ float g_rscT[D_ * S_];
__device__ unsigned short g_A3h[2 * 256 * 128];
__device__ unsigned short g_A3l[2 * 256 * 128];
// packed decW2 limbs: per (ks,ch): 4 uint4, lane j reads uint4 (bh0,bh1,bl0,bl1)
__device__ __align__(16) unsigned short g_dW2p[256 * 256 * 2];

typedef unsigned long long u64;

__device__ __forceinline__ u64 pk(float lo, float hi) {
    u64 r; asm("mov.b64 %0,{%1,%2};" : "=l"(r) : "f"(lo), "f"(hi)); return r;
}
__device__ __forceinline__ void upk(u64 v, float& lo, float& hi) {
    asm("mov.b64 {%0,%1},%2;" : "=f"(lo), "=f"(hi) : "l"(v));
}
__device__ __forceinline__ u64 fma2(u64 a, u64 b, u64 c) {
    u64 d; asm("fma.rn.f32x2 %0,%1,%2,%3;" : "=l"(d) : "l"(a), "l"(b), "l"(c)); return d;
}
__device__ __forceinline__ void split_bf16(float v, unsigned short& h, unsigned short& l) {
    __nv_bfloat16 bh = __float2bfloat16(v);
    float fh = __bfloat162float(bh);
    __nv_bfloat16 bl = __float2bfloat16(v - fh);
    h = __bfloat16_as_ushort(bh);
    l = __bfloat16_as_ushort(bl);
}

#define MMA16816(d0,d1,d2,d3,a0,a1,a2,a3,b0,b1) \
    asm volatile("mma.sync.aligned.m16n8k16.row.col.f32.bf16.bf16.f32 " \
        "{%0,%1,%2,%3}, {%4,%5,%6,%7}, {%8,%9}, {%0,%1,%2,%3};" \
        : "+f"(d0),"+f"(d1),"+f"(d2),"+f"(d3) \
        : "r"(a0),"r"(a1),"r"(a2),"r"(a3),"r"(b0),"r"(b1))

// pointnet dynamic smem layout (bytes)
#define OFF_ALO 0
#define OFF_BH  69632
#define OFF_BL  78336
#define OFF_H1  87040
#define OFF_X   96256
#define SMEMSZ  96640

// ---------------------------------------------------------------------------
// k_prepW3: W3 limb prepack (needed by pointnet). grid 256, 256 threads.
// ---------------------------------------------------------------------------
__global__ __launch_bounds__(256)
void k_prepW3(const float* __restrict__ teW3, const float* __restrict__ reW3)
{
    int idx = blockIdx.x * 256 + threadIdx.x;   // 65536
    int enc = idx >> 15;
    int r   = idx & 32767;
    int ch  = r >> 7;
    int k   = r & 127;
    const float* W3 = enc ? reW3 : teW3;
    float w = W3[k * 256 + ch];
    unsigned short h, l;
    split_bf16(w, h, l);
    g_A3h[idx] = h;
    g_A3l[idx] = l;
}

// ---------------------------------------------------------------------------
// k_prepRest: transpose + packed dW2 + SC1 + P1. grid 1664, 256 threads.
//  [0,256)     transpose var/rsc
//  [256,512)   dW2 packed limb prepack
//  [512,640)   SC1 (8 sources per block)
//  [640,1664)  P1
// ---------------------------------------------------------------------------
__global__ __launch_bounds__(256)
void k_prepRest(const float* __restrict__ var,  const float* __restrict__ rsc,
                const float* __restrict__ decW2,
                const float* __restrict__ src_codes,
                const float* __restrict__ decW1, const float* __restrict__ decb1,
                const float* __restrict__ part_latent)
{
    __shared__ __align__(16) char prepsm[8448];
    const int bid = blockIdx.x, t = threadIdx.x;

    if (bid < 256) {
        float (*tv)[33] = (float(*)[33])prepsm;
        float (*tr)[33] = (float(*)[33])(prepsm + 4224);
        const int tx = t & 31, ty = t >> 5;
        const int s0 = (bid & 31) * 32, k0 = (bid >> 5) * 32;
        #pragma unroll
        for (int jj = 0; jj < 4; ++jj) {
            int s = s0 + ty + jj * 8;
            tv[ty + jj * 8][tx] = var[s * D_ + k0 + tx];
            tr[ty + jj * 8][tx] = rsc[s * D_ + k0 + tx];
        }
        __syncthreads();
        #pragma unroll
        for (int jj = 0; jj < 4; ++jj) {
            int k = k0 + ty + jj * 8;
            g_varT[k * S_ + s0 + tx] = tv[tx][ty + jj * 8];
            g_rscT[k * S_ + s0 + tx] = tr[tx][ty + jj * 8];
        }
    } else if (bid < 512) {
        int idx = (bid - 256) * 256 + t;       // k*256+ch over [0,65536)
        int k  = idx >> 8;
        int ch = idx & 255;
        float w = decW2[k * 256 + ch];
        unsigned short h, l;
        split_bf16(w, h, l);
        int ks = k >> 4, kin = k & 15;
        int jj = (kin >> 1) & 3, hb = kin >> 3, e = kin & 1;
        unsigned base = ((unsigned)(ks * 256 + ch) * 4 + jj) * 8;
        g_dW2p[base + hb * 2 + e]     = h;
        g_dW2p[base + 4 + hb * 2 + e] = l;
    } else if (bid < 640) {
        float (*scs)[256] = (float(*)[256])prepsm;
        const int s0 = (bid - 512) * 8;
        #pragma unroll
        for (int q = 0; q < 8; ++q)
            scs[q][t] = src_codes[(s0 + q) * 256 + t];
        __syncthreads();
        float acc[8];
        float bb = decb1[t];
        #pragma unroll
        for (int q = 0; q < 8; ++q) acc[q] = bb;
        #pragma unroll 4
        for (int i = 0; i < 256; ++i) {
            float w = decW1[(256 + i) * 256 + t];
            #pragma unroll
            for (int q = 0; q < 8; ++q)
                acc[q] = fmaf(scs[q][i], w, acc[q]);
        }
        #pragma unroll
        for (int q = 0; q < 8; ++q)
            g_SC1[(s0 + q) * 256 + t] = acc[q];
    } else {
        float (*part)[32] = (float(*)[32])prepsm;
        const int s = bid - 640;
        ((float*)part)[t]       = part_latent[s * (NPART * 32) + t];
        ((float*)part)[t + 256] = part_latent[s * (NPART * 32) + t + 256];
        __syncthreads();
        float wt[32];
        #pragma unroll
        for (int i = 0; i < 32; ++i)
            wt[i] = decW1[(512 + i) * 256 + t];
        #pragma unroll 2
        for (int p = 0; p < NPART; ++p) {
            float v = 0.f;
            #pragma unroll
            for (int i = 0; i < 32; ++i)
                v = fmaf(part[p][i], wt[i], v);
            g_P1[(s * NPART + p) * 256 + t] = v;
        }
    }
}

// ---------------------------------------------------------------------------
// Kernel 1: PointNet (round-12 exact). grid (64,2), 256 threads.
// ---------------------------------------------------------------------------
__global__ __launch_bounds__(256, 1)
void k_pointnet(const float* __restrict__ noc,
                const float* __restrict__ teW1, const float* __restrict__ teb1,
                const float* __restrict__ teW2, const float* __restrict__ teb2,
                const float* __restrict__ teb3,
                const float* __restrict__ reW1, const float* __restrict__ reb1,
                const float* __restrict__ reW2, const float* __restrict__ reb2,
                const float* __restrict__ reb3)
{
    extern __shared__ char smem[];
    const int b = blockIdx.x;
    const int enc = blockIdx.y;
    const float* W1 = enc ? reW1 : teW1; const float* b1 = enc ? reb1 : teb1;
    const float* W2 = enc ? reW2 : teW2; const float* b2 = enc ? reb2 : teb2;
    const float* b3 = enc ? reb3 : teb3;

    const int t = threadIdx.x;
    const int warp = t >> 5, lane = t & 31;
    const int g = lane >> 2, j = lane & 3;

    unsigned short* ALO = (unsigned short*)(smem + OFF_ALO);
    unsigned short* BHs = (unsigned short*)(smem + OFF_BH);
    unsigned short* BLs = (unsigned short*)(smem + OFF_BL);
    float* H1c = (float*)(smem + OFF_H1);
    float* Xf  = (float*)(smem + OFF_X);
    const uint32_t* ALO32 = (const uint32_t*)ALO;
    const uint32_t* BH32  = (const uint32_t*)BHs;
    const uint32_t* BL32  = (const uint32_t*)BLs;

    {
        const uint4* src = (const uint4*)(g_A3l + enc * 32768);
        #pragma unroll
        for (int i = 0; i < 16; ++i)
            *(uint4*)(ALO + t * 136 + i * 8) = src[t * 16 + i];
    }

    uint32_t ahi[64];
    {
        const uint32_t* AH = (const uint32_t*)(g_A3h + enc * 32768);
        #pragma unroll
        for (int mt = 0; mt < 2; ++mt) {
            const int r0 = warp * 32 + mt * 16 + g;
            #pragma unroll
            for (int ks = 0; ks < 8; ++ks) {
                const int fi = (mt * 8 + ks) * 4;
                ahi[fi + 0] = AH[r0 * 64 + j + 8 * ks];
                ahi[fi + 1] = AH[(r0 + 8) * 64 + j + 8 * ks];
                ahi[fi + 2] = AH[r0 * 64 + j + 4 + 8 * ks];
                ahi[fi + 3] = AH[(r0 + 8) * 64 + j + 4 + 8 * ks];
            }
        }
    }

    const int colB = t & 63, pgB = t >> 6;
    const int c0C = (t & 31) * 4, pgC = t >> 5;
    const float w10 = W1[colB], w11 = W1[64 + colB], w12 = W1[128 + colB];
    const float bb1 = b1[colB];
    const float4 bb2 = *(const float4*)&b2[c0C];
    const u64 bb2p[4] = { pk(bb2.x, bb2.x), pk(bb2.y, bb2.y),
                          pk(bb2.z, bb2.z), pk(bb2.w, bb2.w) };

    float dmax[4] = { -1e30f, -1e30f, -1e30f, -1e30f };

    #pragma unroll 1
    for (int chunk = 0; chunk < 32; ++chunk) {
        __syncthreads();
        if (t < 96) {
            int c = t >> 5, p = t & 31;
            Xf[c * 32 + p] = noc[b * 3072 + c * 1024 + chunk * 32 + p];
        }
        __syncthreads();

        {
            float v[8];
            #pragma unroll
            for (int pp = 0; pp < 8; ++pp) {
                int p = pgB * 8 + pp;
                float h = fmaf(Xf[p], w10, fmaf(Xf[32 + p], w11, fmaf(Xf[64 + p], w12, bb1)));
                v[pp] = fmaxf(h, 0.f);
            }
            #pragma unroll
            for (int q = 0; q < 4; ++q)
                *(u64*)&H1c[colB * 36 + pgB * 8 + 2 * q] = pk(v[2*q], v[2*q+1]);
        }
        __syncthreads();

        {
            u64 acc[2][4];
            #pragma unroll
            for (int q = 0; q < 2; ++q)
                #pragma unroll
                for (int jj = 0; jj < 4; ++jj) acc[q][jj] = bb2p[jj];
            #pragma unroll 4
            for (int k = 0; k < 64; ++k) {
                ulonglong2 xa = *(const ulonglong2*)&H1c[k * 36 + pgC * 4];
                float4 w = *(const float4*)&W2[k * 128 + c0C];
                u64 wp0 = pk(w.x, w.x), wp1 = pk(w.y, w.y);
                u64 wp2 = pk(w.z, w.z), wp3 = pk(w.w, w.w);
                acc[0][0] = fma2(xa.x, wp0, acc[0][0]);
                acc[0][1] = fma2(xa.x, wp1, acc[0][1]);
                acc[0][2] = fma2(xa.x, wp2, acc[0][2]);
                acc[0][3] = fma2(xa.x, wp3, acc[0][3]);
                acc[1][0] = fma2(xa.y, wp0, acc[1][0]);
                acc[1][1] = fma2(xa.y, wp1, acc[1][1]);
                acc[1][2] = fma2(xa.y, wp2, acc[1][2]);
                acc[1][3] = fma2(xa.y, wp3, acc[1][3]);
            }
            float vals[4][4];
            #pragma unroll
            for (int q = 0; q < 2; ++q)
                #pragma unroll
                for (int jj = 0; jj < 4; ++jj)
                    upk(acc[q][jj], vals[2*q][jj], vals[2*q+1][jj]);
            #pragma unroll
            for (int p = 0; p < 4; ++p) {
                int n = pgC * 4 + p;
                unsigned short h[4], l[4];
                #pragma unroll
                for (int jj = 0; jj < 4; ++jj)
                    split_bf16(fmaxf(vals[p][jj], 0.f), h[jj], l[jj]);
                u64 hp = (u64)h[0] | ((u64)h[1] << 16) | ((u64)h[2] << 32) | ((u64)h[3] << 48);
                u64 lp = (u64)l[0] | ((u64)l[1] << 16) | ((u64)l[2] << 32) | ((u64)l[3] << 48);
                *(u64*)((char*)BHs + n * 272 + c0C * 2) = hp;
                *(u64*)((char*)BLs + n * 272 + c0C * 2) = lp;
            }
        }
        __syncthreads();

        float d[2][4][4];
        #pragma unroll
        for (int mt = 0; mt < 2; ++mt)
            #pragma unroll
            for (int nt = 0; nt < 4; ++nt)
                #pragma unroll
                for (int e = 0; e < 4; ++e) d[mt][nt][e] = 0.f;

        #pragma unroll
        for (int ks = 0; ks < 8; ++ks) {
            uint32_t bh0[4], bh1[4], bl0[4], bl1[4];
            #pragma unroll
            for (int nt = 0; nt < 4; ++nt) {
                const uint32_t* BHrow = BH32 + (nt * 8 + g) * 68;
                const uint32_t* BLrow = BL32 + (nt * 8 + g) * 68;
                bh0[nt] = BHrow[j + 8 * ks];
                bh1[nt] = BHrow[j + 4 + 8 * ks];
                bl0[nt] = BLrow[j + 8 * ks];
                bl1[nt] = BLrow[j + 4 + 8 * ks];
            }
            #pragma unroll
            for (int mt = 0; mt < 2; ++mt) {
                const int fi = (mt * 8 + ks) * 4;
                uint32_t a0 = ahi[fi], a1 = ahi[fi+1], a2 = ahi[fi+2], a3 = ahi[fi+3];
                #pragma unroll
                for (int nt = 0; nt < 4; ++nt) {
                    MMA16816(d[mt][nt][0], d[mt][nt][1], d[mt][nt][2], d[mt][nt][3],
                             a0, a1, a2, a3, bh0[nt], bh1[nt]);
                    MMA16816(d[mt][nt][0], d[mt][nt][1], d[mt][nt][2], d[mt][nt][3],
                             a0, a1, a2, a3, bl0[nt], bl1[nt]);
                }
                const int r0 = warp * 32 + mt * 16 + g;
                uint32_t l0 = ALO32[r0 * 68 + j + 8 * ks];
                uint32_t l1 = ALO32[(r0 + 8) * 68 + j + 8 * ks];
                uint32_t l2 = ALO32[r0 * 68 + j + 4 + 8 * ks];
                uint32_t l3 = ALO32[(r0 + 8) * 68 + j + 4 + 8 * ks];
                #pragma unroll
                for (int nt = 0; nt < 4; ++nt)
                    MMA16816(d[mt][nt][0], d[mt][nt][1], d[mt][nt][2], d[mt][nt][3],
                             l0, l1, l2, l3, bh0[nt], bh1[nt]);
            }
        }

        #pragma unroll
        for (int mt = 0; mt < 2; ++mt)
            #pragma unroll
            for (int nt = 0; nt < 4; ++nt) {
                dmax[mt*2+0] = fmaxf(dmax[mt*2+0], fmaxf(d[mt][nt][0], d[mt][nt][1]));
                dmax[mt*2+1] = fmaxf(dmax[mt*2+1], fmaxf(d[mt][nt][2], d[mt][nt][3]));
            }
    }

    #pragma unroll
    for (int e = 0; e < 4; ++e) {
        dmax[e] = fmaxf(dmax[e], __shfl_xor_sync(0xffffffffu, dmax[e], 1));
        dmax[e] = fmaxf(dmax[e], __shfl_xor_sync(0xffffffffu, dmax[e], 2));
    }
    if (j == 0) {
        #pragma unroll
        for (int mt = 0; mt < 2; ++mt)
            #pragma unroll
            for (int hf = 0; hf < 2; ++hf) {
                int ch = warp * 32 + mt * 16 + hf * 8 + g;
                g_pool[(enc * B_ + b) * D_ + ch] = fmaxf(dmax[mt*2+hf] + b3[ch], 0.f);
            }
    }
}

// ---------------------------------------------------------------------------
// Kernel 2: fused fc + distances + exact top-10. grid 64, 256 threads.
// ---------------------------------------------------------------------------
__global__ __launch_bounds__(256, 1)
void k_fcdist(const float* __restrict__ teWf, const float* __restrict__ tebf,
              const float* __restrict__ reWf, const float* __restrict__ rebf,
              const float* __restrict__ decW1)
{
    const int b = blockIdx.x, t = threadIdx.x;
    __shared__ float ste[256], rets[256], stgt[256];
    __shared__ float d[1024];
    __shared__ float sval[256];
    __shared__ int   sidx[256];

    ste[t] = g_pool[b * D_ + t];
    d[t]   = g_pool[(B_ + b) * D_ + t];
    __syncthreads();

    float a = tebf[t], r = rebf[t];
    #pragma unroll 8
    for (int i = 0; i < 256; ++i) {
        a = fmaf(ste[i], teWf[i * 256 + t], a);
        r = fmaf(d[i],   reWf[i * 256 + t], r);
    }
    rets[t] = r;
    stgt[t] = a;
    __syncthreads();

    float tv = 0.f;
    #pragma unroll 8
    for (int i = 0; i < 256; ++i)
        tv = fmaf(stgt[i], decW1[i * 256 + t], tv);
    g_T[b * D_ + t] = tv;

    const int s4 = 4 * t;
    float a0 = 0.f, a1 = 0.f, a2 = 0.f, a3 = 0.f;
    #pragma unroll 4
    for (int k = 0; k < 256; ++k) {
        float rr = rets[k];
        float4 v = *(const float4*)&g_varT[k * S_ + s4];
        float4 c = *(const float4*)&g_rscT[k * S_ + s4];
        float d0 = rr - c.x, d1 = rr - c.y, d2 = rr - c.z, d3 = rr - c.w;
        a0 = fmaf(v.x, d0 * d0, a0);
        a1 = fmaf(v.y, d1 * d1, a1);
        a2 = fmaf(v.z, d2 * d2, a2);
        a3 = fmaf(v.w, d3 * d3, a3);
    }
    d[s4] = a0; d[s4 + 1] = a1; d[s4 + 2] = a2; d[s4 + 3] = a3;
    __syncthreads();

    for (int it = 0; it < KRET; ++it) {
        float bv = 1e30f; int bi = S_;
        #pragma unroll
        for (int q = 0; q < 4; ++q) {
            int s = q * 256 + t;
            float v = d[s];
            if (v < bv || (v == bv && s < bi)) { bv = v; bi = s; }
        }
        sval[t] = bv; sidx[t] = bi;
        __syncthreads();
        for (int off = 128; off > 0; off >>= 1) {
            if (t < off) {
                float v2 = sval[t + off]; int i2 = sidx[t + off];
                if (v2 < sval[t] || (v2 == sval[t] && i2 < sidx[t])) {
                    sval[t] = v2; sidx[t] = i2;
                }
            }
            __syncthreads();
        }
        if (t == 0) {
            g_idx[b * KRET + it] = sidx[0];
            d[sidx[0]] = 1e30f;
        }
        __syncthreads();
    }
}

// ---------------------------------------------------------------------------
// Kernel 4: decoder MLP via mma.sync (round-14 structure, packed B LDG.128).
// grid 640, 256 threads, 4 CTAs/SM.
// ---------------------------------------------------------------------------
__global__ __launch_bounds__(256, 4)
void k_decode_mlp(const float* __restrict__ decb2,
                  const float* __restrict__ decW3, const float* __restrict__ decb3,
                  const float* __restrict__ proj,  const float* __restrict__ defp)
{
    const int bk = blockIdx.x;
    const int b = bk / KRET;
    const int t = threadIdx.x;
    const int s = g_idx[bk];
    const int warp = t >> 5, lane = t & 31;
    const int g = lane >> 2, j = lane & 3;

    __shared__ __align__(16) unsigned short AH1[16 * 264];
    __shared__ __align__(16) unsigned short AL1[16 * 264];
    __shared__ float H2f[256 * 20];
    __shared__ float raw[NPAR];

    // ---- H1: base + P1, relu, split limbs into A tiles (k-col = t) ----
    {
        float base = g_T[b * D_ + t] + g_SC1[s * 256 + t];
        const float* p1 = &g_P1[s * (NPART * 256) + t];
        #pragma unroll
        for (int p = 0; p < NPART; ++p) {
            float v = fmaxf(base + p1[p * 256], 0.f);
            unsigned short h, l;
            split_bf16(v, h, l);
            AH1[p * 264 + t] = h;
            AL1[p * 264 + t] = l;
        }
    }
    __syncthreads();

    // ---- H2 via MMA: warp -> 32 chs (4 n8-tiles), 16 ksteps ----
    {
        const uint32_t* A1H32 = (const uint32_t*)AH1;
        const uint32_t* A1L32 = (const uint32_t*)AL1;
        const uint4* Wp = (const uint4*)g_dW2p;   // [(ks*256+ch)*4 + j]
        const int chb = warp * 32;

        float d[4][4];
        #pragma unroll
        for (int nt = 0; nt < 4; ++nt)
            #pragma unroll
            for (int e = 0; e < 4; ++e) d[nt][e] = 0.f;

        #pragma unroll 4
        for (int ks = 0; ks < 16; ++ks) {
            uint32_t ah0 = A1H32[g * 132 + j + 8 * ks];
            uint32_t ah1 = A1H32[(g + 8) * 132 + j + 8 * ks];
            uint32_t ah2 = A1H32[g * 132 + j + 4 + 8 * ks];
            uint32_t ah3 = A1H32[(g + 8) * 132 + j + 4 + 8 * ks];
            uint32_t al0 = A1L32[g * 132 + j + 8 * ks];
            uint32_t al1 = A1L32[(g + 8) * 132 + j + 8 * ks];
            uint32_t al2 = A1L32[g * 132 + j + 4 + 8 * ks];
            uint32_t al3 = A1L32[(g + 8) * 132 + j + 4 + 8 * ks];
            #pragma unroll
            for (int nt = 0; nt < 4; ++nt) {
                const int ch = chb + nt * 8 + g;
                uint4 W = Wp[(ks * 256 + ch) * 4 + j];   // bh0,bh1,bl0,bl1
                MMA16816(d[nt][0], d[nt][1], d[nt][2], d[nt][3],
                         ah0, ah1, ah2, ah3, W.x, W.y);
                MMA16816(d[nt][0], d[nt][1], d[nt][2], d[nt][3],
                         ah0, ah1, ah2, ah3, W.z, W.w);
                MMA16816(d[nt][0], d[nt][1], d[nt][2], d[nt][3],
                         al0, al1, al2, al3, W.x, W.y);
            }
        }

        // epilogue: bias + relu -> H2f[ch][part]
        #pragma unroll
        for (int nt = 0; nt < 4; ++nt) {
            const int ch0 = chb + nt * 8 + 2 * j;
            float bb0 = decb2[ch0], bb1 = decb2[ch0 + 1];
            H2f[ch0 * 20 + g]           = fmaxf(d[nt][0] + bb0, 0.f);
            H2f[(ch0 + 1) * 20 + g]     = fmaxf(d[nt][1] + bb1, 0.f);
            H2f[ch0 * 20 + g + 8]       = fmaxf(d[nt][2] + bb0, 0.f);
            H2f[(ch0 + 1) * 20 + g + 8] = fmaxf(d[nt][3] + bb1, 0.f);
        }
    }
    __syncthreads();

    // ---- raw = H2 @ W3 + b3 ----
    if (t < NPAR) {
        const int p = t / 6, o = t % 6;
        float v = decb3[o];
        #pragma unroll 8
        for (int k = 0; k < 256; ++k)
            v = fmaf(H2f[k * 20 + p], decW3[k * 6 + o], v);
        raw[t] = v;
    }
    __syncthreads();

    // ---- params = proj[s] @ raw + def[s] ----
    if (t < NPAR) {
        float v = defp[s * NPAR + t];
        const float* pr = proj + (size_t)s * NPAR * NPAR + t * NPAR;
        #pragma unroll 8
        for (int jj = 0; jj < NPAR; ++jj)
            v = fmaf(pr[jj], raw[jj], v);
        g_par[bk * NPAR + t] = v;
    }
}

// ---------------------------------------------------------------------------
// Kernel 5: deformation (round-12 smem-staged form). grid (640, 6).
// ---------------------------------------------------------------------------
__global__ __launch_bounds__(256)
void k_deform(const float* __restrict__ mat, float* __restrict__ out)
{
    const int bk = blockIdx.x;
    const int t = threadIdx.x;
    const int s = g_idx[bk];
    __shared__ float par[NPAR];
    __shared__ __align__(16) float tilebuf[64 * 104];
    if (t < NPAR) par[t] = g_par[bk * NPAR + t];

    const float* mb = mat + (size_t)s * PSRC3 * NPAR;
    float* ob = out + (size_t)bk * PSRC3;
    const int row = t >> 2, q = t & 3;

    #pragma unroll 1
    for (int tile = 0; tile < 4; ++tile) {
        const int R0 = blockIdx.y * 256 + tile * 64;
        __syncthreads();
        const float4* src = (const float4*)(mb + (size_t)R0 * NPAR);
        #pragma unroll
        for (int i = 0; i < 6; ++i) {
            int idx = i * 256 + t;
            int r = idx / 24, c = idx % 24;
            *(float4*)&tilebuf[r * 104 + c * 4] = src[idx];
        }
        __syncthreads();
        float v = 0.f;
        const float* tb = &tilebuf[row * 104 + q * 24];
        const float* pq = &par[q * 24];
        #pragma unroll
        for (int i4 = 0; i4 < 6; ++i4) {
            float4 m4 = *(const float4*)&tb[i4 * 4];
            v = fmaf(m4.x, pq[i4 * 4 + 0], v);
            v = fmaf(m4.y, pq[i4 * 4 + 1], v);
            v = fmaf(m4.z, pq[i4 * 4 + 2], v);
            v = fmaf(m4.w, pq[i4 * 4 + 3], v);
        }
        v += __shfl_xor_sync(0xffffffffu, v, 1);
        v += __shfl_xor_sync(0xffffffffu, v, 2);
        if (q == 0)
            ob[R0 + row] = v;
    }
}

// ---------------------------------------------------------------------------
extern "C" void kernel_launch(void* const* d_in, const int* in_sizes, int n_in,
                              void* d_out, int out_size)
{
    const float* noc  = (const float*)d_in[0];
    const float* teW1 = (const float*)d_in[1];  const float* teb1 = (const float*)d_in[2];
    const float* teW2 = (const float*)d_in[3];  const float* teb2 = (const float*)d_in[4];
    const float* teW3 = (const float*)d_in[5];  const float* teb3 = (const float*)d_in[6];
    const float* teWf = (const float*)d_in[7];  const float* tebf = (const float*)d_in[8];
    const float* reW1 = (const float*)d_in[9];  const float* reb1 = (const float*)d_in[10];
    const float* reW2 = (const float*)d_in[11]; const float* reb2 = (const float*)d_in[12];
    const float* reW3 = (const float*)d_in[13]; const float* reb3 = (const float*)d_in[14];
    const float* reWf = (const float*)d_in[15]; const float* rebf = (const float*)d_in[16];
    const float* decW1 = (const float*)d_in[17]; const float* decb1 = (const float*)d_in[18];
    const float* decW2 = (const float*)d_in[19]; const float* decb2 = (const float*)d_in[20];
    const float* decW3 = (const float*)d_in[21]; const float* decb3 = (const float*)d_in[22];
    const float* ret_src = (const float*)d_in[23];
    const float* src_codes = (const float*)d_in[24];
    const float* src_var = (const float*)d_in[25];
    const float* part_latent = (const float*)d_in[26];
    const float* defp = (const float*)d_in[27];
    const float* proj = (const float*)d_in[28];
    const float* mat  = (const float*)d_in[29];
    float* out = (float*)d_out;

    static cudaStream_t s2 = nullptr;
    static cudaEvent_t evFork = nullptr, evJoin = nullptr;
    if (!s2) {
        cudaStreamCreateWithFlags(&s2, cudaStreamNonBlocking);
        cudaEventCreateWithFlags(&evFork, cudaEventDisableTiming);
        cudaEventCreateWithFlags(&evJoin, cudaEventDisableTiming);
    }

    cudaFuncSetAttribute(k_pointnet, cudaFuncAttributeMaxDynamicSharedMemorySize, SMEMSZ);

    // fork: prepRest (transpose/dW2/SC1/P1) overlaps pointnet on idle SMs
    cudaEventRecord(evFork, 0);
    cudaStreamWaitEvent(s2, evFork, 0);
    k_prepRest<<<1664, 256, 0, s2>>>(src_var, ret_src, decW2,
                                     src_codes, decW1, decb1, part_latent);
    cudaEventRecord(evJoin, s2);

    k_prepW3<<<256, 256>>>(teW3, reW3);
    dim3 g1(B_, 2);
    k_pointnet<<<g1, 256, SMEMSZ>>>(noc, teW1, teb1, teW2, teb2, teb3,
                                    reW1, reb1, reW2, reb2, reb3);

    cudaStreamWaitEvent(0, evJoin, 0);
    k_fcdist<<<B_, 256>>>(teWf, tebf, reWf, rebf, decW1);
    k_decode_mlp<<<B_ * KRET, 256>>>(decb2, decW3, decb3, proj, defp);
    dim3 g5(B_ * KRET, 6);
    k_deform<<<g5, 256>>>(mat, out);
}